// round 16
// baseline (speedup 1.0000x reference)
#include <cuda_runtime.h>
#include <cuda_fp16.h>
#include <math.h>
#include <stdint.h>

#define NB 4
#define NP 8
#define NN 512
#define DM 128
#define NH 4
#define DK 32
#define NT 3
#define NROWS (NB*NP*NN)     // 16384
#define MAXNNZ 128
#define LISTD 132
#define LDP 132              // smem row stride (floats) for fp32 epilogue scratch
#define LDH 68               // smem row stride (uint32 = half2) for fp16 tiles

// Scratch (device globals). fp16 intermediates to halve HBM traffic.
__device__ __half g_Xh[NROWS][DM];       // inputs pre-converted to fp16
__device__ __half g_Wh[9][DM][DM];       // Wq/Wk/Wv pre-converted to fp16
__device__ __half g_Woh[DM][NT*DM];      // Wo pre-converted to fp16
__device__ __half g_qkv[9][NROWS][DM];   // [t*3 + {Q,K,V}][row][d]
__device__ __half g_attn[NT][NROWS][DM]; // per-t attention output (fp16)
__device__ int    g_nnz[NT][NN];
__device__ int    g_colsT[NT][LISTD][NN];   // [t][i][n] -> coalesced over n
__device__ float  g_valsT[NT][LISTD][NN];

__constant__ int c_which[NT] = {0, 1, 3};

// ---------------------------------------------------------------------------
__device__ __forceinline__ uint32_t pack_h2(float a, float b) {
    __half2 h = __floats2half2_rn(a, b);
    return *(uint32_t*)&h;
}
__device__ __forceinline__ __half2 u2h2(uint32_t u) { return *(__half2*)&u; }
// m16n8k16 fp16 MMA, fp32 accum, D += A*B (row x col)
__device__ __forceinline__ void mma16(float d[4], const uint32_t a[4], const uint32_t b[2]) {
    asm volatile("mma.sync.aligned.m16n8k16.row.col.f32.f16.f16.f32 "
        "{%0,%1,%2,%3}, {%4,%5,%6,%7}, {%8,%9}, {%0,%1,%2,%3};"
        : "+f"(d[0]), "+f"(d[1]), "+f"(d[2]), "+f"(d[3])
        : "r"(a[0]), "r"(a[1]), "r"(a[2]), "r"(a[3]), "r"(b[0]), "r"(b[1]));
}

// ===========================================================================
// Kernel 0: pre-convert X, the 9 QKV weight slots, and Wo to fp16.
// ===========================================================================
#define XV  (NROWS*DM/8)     // 262144
#define WV  (9*DM*DM/8)      // 18432
#define WOV (DM*NT*DM/8)     // 6144
__global__ void convert_kernel(const float* __restrict__ X,
                               const float* __restrict__ Wq,
                               const float* __restrict__ Wk,
                               const float* __restrict__ Wv,
                               const float* __restrict__ Wo) {
    int idx = blockIdx.x * blockDim.x + threadIdx.x;
    if (idx < XV) {
        const float4* s = (const float4*)X + (size_t)idx * 2;
        float4 a = s[0], b = s[1];
        uint4 p = make_uint4(pack_h2(a.x, a.y), pack_h2(a.z, a.w),
                             pack_h2(b.x, b.y), pack_h2(b.z, b.w));
        *(uint4*)(&g_Xh[0][0] + (size_t)idx * 8) = p;
    } else if (idx < XV + WV) {
        int w = idx - XV;
        int slot = w / (DM * DM / 8);
        int off  = w % (DM * DM / 8);
        const float* Wb3[3] = {Wq, Wk, Wv};
        const float4* s = (const float4*)(Wb3[slot % 3] + (size_t)(slot / 3) * DM * DM) + (size_t)off * 2;
        float4 a = s[0], b = s[1];
        uint4 p = make_uint4(pack_h2(a.x, a.y), pack_h2(a.z, a.w),
                             pack_h2(b.x, b.y), pack_h2(b.z, b.w));
        *(uint4*)(&g_Wh[slot][0][0] + (size_t)off * 8) = p;
    } else if (idx < XV + WV + WOV) {
        int off = idx - XV - WV;
        const float4* s = (const float4*)Wo + (size_t)off * 2;
        float4 a = s[0], b = s[1];
        uint4 p = make_uint4(pack_h2(a.x, a.y), pack_h2(a.z, a.w),
                             pack_h2(b.x, b.y), pack_h2(b.z, b.w));
        *(uint4*)(&g_Woh[0][0] + (size_t)off * 8) = p;
    }
}

// ===========================================================================
// Kernel 1: build transposed CSR of the selected transition matrices.
// ===========================================================================
__global__ void build_csr_kernel(const float* __restrict__ tmall) {
    int wg   = (blockIdx.x * blockDim.x + threadIdx.x) >> 5;
    int lane = threadIdx.x & 31;
    if (wg >= NT * NN) return;
    int t = wg / NN, n = wg % NN;
    const float* row = tmall + ((size_t)c_which[t] * NN + n) * NN;
    int cnt = 0;
    for (int base = 0; base < NN; base += 32) {
        float v = row[base + lane];
        unsigned b = __ballot_sync(0xffffffffu, v != 0.0f);
        if (v != 0.0f) {
            int pos = cnt + __popc(b & ((1u << lane) - 1u));
            if (pos < MAXNNZ) { g_colsT[t][pos][n] = base + lane; g_valsT[t][pos][n] = v; }
        }
        cnt += __popc(b);
    }
    if (lane == 0) g_nnz[t][n] = cnt < MAXNNZ ? cnt : MAXNNZ;
}

// ===========================================================================
// Kernel 2: QKV projections via fp16 mma.sync m16n8k16. 128-row tiles,
// grid = (128 tiles, 9 slots); 256 threads / 8 warps as 4(m) x 2(n), each
// warp a 32x64 tile; 2 CTAs/SM (68KB smem). Halves W L2 traffic vs 64-row.
// ===========================================================================
__global__ void __launch_bounds__(256, 2)
qkv_mma_kernel() {
    extern __shared__ uint32_t sm[];
    uint32_t* Xh = sm;                // [128][LDH]
    uint32_t* Wh = sm + 128 * LDH;    // [128][LDH]
    int tid = threadIdx.x, lane = tid & 31, wid = tid >> 5;
    int mw = wid & 3, nw = wid >> 2;
    int g = lane >> 2, q = lane & 3;
    int slot = blockIdx.y;
    int row0 = blockIdx.x * 128;

    const __half* Xg = &g_Xh[row0][0];
    for (int i = tid; i < 128 * 16; i += 256) {
        int r = i >> 4, c = i & 15;
        uint4 v = *(const uint4*)(Xg + (size_t)r * DM + c * 8);
        *(uint4*)(Xh + r * LDH + c * 4) = v;
    }
    const __half* Wg = &g_Wh[slot][0][0];
    for (int i = tid; i < 128 * 16; i += 256) {
        int r = i >> 4, c = i & 15;
        uint4 v = *(const uint4*)(Wg + (size_t)r * DM + c * 8);
        *(uint4*)(Wh + r * LDH + c * 4) = v;
    }
    __syncthreads();

    const uint32_t* abase = Xh + (mw * 32 + g) * LDH + q;
    const uint32_t* bbase = Wh + (nw * 64 + g) * LDH + q;

    float acc[2][8][4];
    #pragma unroll
    for (int t2 = 0; t2 < 2; t2++)
        #pragma unroll
        for (int j = 0; j < 8; j++)
            #pragma unroll
            for (int e = 0; e < 4; e++) acc[t2][j][e] = 0.f;

    #pragma unroll
    for (int ks = 0; ks < 8; ks++) {
        int k0 = ks * 8;
        uint32_t a[2][4];
        #pragma unroll
        for (int t2 = 0; t2 < 2; t2++) {
            const uint32_t* ap = abase + t2 * 16 * LDH + k0;
            a[t2][0] = ap[0];            a[t2][1] = ap[8 * LDH];
            a[t2][2] = ap[4];            a[t2][3] = ap[8 * LDH + 4];
        }
        #pragma unroll
        for (int j = 0; j < 8; j++) {
            const uint32_t* bp = bbase + j * 8 * LDH + k0;
            uint32_t b[2]; b[0] = bp[0]; b[1] = bp[4];
            mma16(acc[0][j], a[0], b);
            mma16(acc[1][j], a[1], b);
        }
    }
    __half* outh = &g_qkv[slot][row0][0];
    #pragma unroll
    for (int t2 = 0; t2 < 2; t2++) {
        int r = mw * 32 + t2 * 16 + g;
        #pragma unroll
        for (int j = 0; j < 8; j++) {
            int c = nw * 64 + j * 8 + q * 2;
            *(uint32_t*)(outh + (size_t)r * DM + c)       = pack_h2(acc[t2][j][0], acc[t2][j][1]);
            *(uint32_t*)(outh + (size_t)(r + 8) * DM + c) = pack_h2(acc[t2][j][2], acc[t2][j][3]);
        }
    }
}

// ===========================================================================
// Kernel 3: sparse-masked attention (R15 structure, unchanged).
//  - K in fp16 SMEM, duplicated-row layout (4 LDS.128/entry, 4-phase);
//    dot via 16 HFMA2 in 4 parallel chains, combined in fp32.
//  - V in fp32 SMEM, rotated layout (8 LDS.128/entry, 4-phase), fp32 FFMA.
// ===========================================================================
__global__ void __launch_bounds__(512, 1)
attn_kernel() {
    extern __shared__ uint32_t smw[];
    uint32_t* Ks = smw;                 // [512][32] uint32: 16 data + 16 dup
    float*    Vs = (float*)(smw + 512 * 32);  // [512][32] fp32
    int tid = threadIdx.x;
    int h = blockIdx.x;
    int t = blockIdx.y >> 5, bp = blockIdx.y & 31;

    const __half* Kg = &g_qkv[t * 3 + 1][(size_t)bp * NN][0];
    const __half* Vg = &g_qkv[t * 3 + 2][(size_t)bp * NN][0];
    for (int i = tid; i < 512 * 4; i += 512) {
        int m = i >> 2, c = i & 3;
        uint4 kk = *(const uint4*)(Kg + (size_t)m * DM + h * DK + c * 8);
        *(uint4*)(Ks + m * 32 + c * 4)      = kk;
        *(uint4*)(Ks + m * 32 + 16 + c * 4) = kk;
        uint4 vv = *(const uint4*)(Vg + (size_t)m * DM + h * DK + c * 8);
        float2 f0 = __half22float2(u2h2(vv.x));
        float2 f1 = __half22float2(u2h2(vv.y));
        float2 f2 = __half22float2(u2h2(vv.z));
        float2 f3 = __half22float2(u2h2(vv.w));
        *(float4*)(Vs + m * 32 + c * 8)     = make_float4(f0.x, f0.y, f1.x, f1.y);
        *(float4*)(Vs + m * 32 + c * 8 + 4) = make_float4(f2.x, f2.y, f3.x, f3.y);
    }
    __syncthreads();

    int n = tid;
    int gn = bp * NN + n;
    int rot4 = tid & 3;
    int copyoff = ((tid >> 2) & 1) * 16;
    int rot8 = tid & 7;
    const float scale = 0.17677669529663687f;
    const __half2 sh2 = __float2half2_rn(scale);

    __half2 qh[16];
    const __half* Qg = &g_qkv[t * 3 + 0][gn][h * DK];
    #pragma unroll
    for (int c = 0; c < 4; c++) {
        int cc = (c + rot4) & 3;
        uint4 qv = *(const uint4*)(Qg + cc * 8);
        qh[c * 4 + 0] = __hmul2(u2h2(qv.x), sh2);
        qh[c * 4 + 1] = __hmul2(u2h2(qv.y), sh2);
        qh[c * 4 + 2] = __hmul2(u2h2(qv.z), sh2);
        qh[c * 4 + 3] = __hmul2(u2h2(qv.w), sh2);
    }
    int cnt = g_nnz[t][n];
    float Z = 0.f;
    float4 av[8];
    #pragma unroll
    for (int j = 0; j < 8; j++) av[j] = make_float4(0.f, 0.f, 0.f, 0.f);

    for (int i = 0; i < cnt; i++) {
        int m = g_colsT[t][i][n];
        float tv = g_valsT[t][i][n];
        const uint32_t* kb = Ks + m * 32 + copyoff;
        __half2 hacc[4];
        #pragma unroll
        for (int c = 0; c < 4; c++) {
            uint4 kk = *(const uint4*)(kb + ((c + rot4) & 3) * 4);
            __half2 a = __hmul2(qh[c * 4 + 0], u2h2(kk.x));
            a = __hfma2(qh[c * 4 + 1], u2h2(kk.y), a);
            a = __hfma2(qh[c * 4 + 2], u2h2(kk.z), a);
            a = __hfma2(qh[c * 4 + 3], u2h2(kk.w), a);
            hacc[c] = a;
        }
        float2 f0 = __half22float2(hacc[0]);
        float2 f1 = __half22float2(hacc[1]);
        float2 f2 = __half22float2(hacc[2]);
        float2 f3 = __half22float2(hacc[3]);
        float s = ((f0.x + f0.y) + (f1.x + f1.y)) + ((f2.x + f2.y) + (f3.x + f3.y));
        float e = __expf(s);
        Z += e;
        float we = tv * e;
        const float* vb = Vs + m * 32;
        #pragma unroll
        for (int j = 0; j < 8; j++) {
            int jj = (j + rot8) & 7;
            float4 v4 = *(const float4*)(vb + jj * 4);
            av[j].x += we * v4.x;
            av[j].y += we * v4.y;
            av[j].z += we * v4.z;
            av[j].w += we * v4.w;
        }
    }
    float inv = 1.f / Z;
    __half* outh = &g_attn[t][gn][h * DK];
    #pragma unroll
    for (int j = 0; j < 8; j += 2) {
        int j0 = (j + rot8) & 7, j1 = (j + 1 + rot8) & 7;
        *(uint2*)(outh + j0 * 4) = make_uint2(pack_h2(av[j].x * inv, av[j].y * inv),
                                              pack_h2(av[j].z * inv, av[j].w * inv));
        *(uint2*)(outh + j1 * 4) = make_uint2(pack_h2(av[j+1].x * inv, av[j+1].y * inv),
                                              pack_h2(av[j+1].z * inv, av[j+1].w * inv));
    }
}

// ===========================================================================
// Kernel 4: output projection via fp16 mma.sync m16n8k16 (K=384 = 3
// accumulated chunks), 512 threads / 16 warps; A and W both staged as raw
// uint4 copies from fp16 globals. Fused residual + warp-per-row LN.
// ===========================================================================
__global__ void __launch_bounds__(512, 1)
outproj_mma_kernel(const float* __restrict__ X,
                   const float* __restrict__ gamma,
                   const float* __restrict__ beta,
                   float* __restrict__ out) {
    extern __shared__ uint32_t sm[];
    uint32_t* As = sm;                 // [128][LDH]
    uint32_t* Ws = sm + 128 * LDH;     // [128][LDH]
    float* Ys = (float*)sm;            // reuse (LDP stride) after GEMM
    int tid = threadIdx.x, lane = tid & 31, wid = tid >> 5;
    int mw = wid & 3, nw = wid >> 2;
    int g = lane >> 2, q = lane & 3;
    int row0 = blockIdx.x * 128;

    const uint32_t* abase = As + (mw * 32 + g) * LDH + q;
    const uint32_t* bbase = Ws + (nw * 32 + g) * LDH + q;

    float acc[2][4][4];
    #pragma unroll
    for (int t2 = 0; t2 < 2; t2++)
        #pragma unroll
        for (int j = 0; j < 4; j++)
            #pragma unroll
            for (int e = 0; e < 4; e++) acc[t2][j][e] = 0.f;

    for (int t = 0; t < NT; t++) {
        __syncthreads();
        for (int i = tid; i < 128 * 16; i += 512) {
            int r = i >> 4, c = i & 15;
            uint4 a = *(const uint4*)(&g_attn[t][row0 + r][c * 8]);
            *(uint4*)(As + r * LDH + c * 4) = a;
        }
        for (int i = tid; i < 128 * 16; i += 512) {
            int r = i >> 4, c = i & 15;
            uint4 w = *(const uint4*)(&g_Woh[r][t * DM + c * 8]);
            *(uint4*)(Ws + r * LDH + c * 4) = w;
        }
        __syncthreads();
        #pragma unroll
        for (int ks = 0; ks < 8; ks++) {
            int k0 = ks * 8;
            uint32_t a[2][4];
            #pragma unroll
            for (int t2 = 0; t2 < 2; t2++) {
                const uint32_t* ap = abase + t2 * 16 * LDH + k0;
                a[t2][0] = ap[0];            a[t2][1] = ap[8 * LDH];
                a[t2][2] = ap[4];            a[t2][3] = ap[8 * LDH + 4];
            }
            #pragma unroll
            for (int j = 0; j < 4; j++) {
                const uint32_t* bp = bbase + j * 8 * LDH + k0;
                uint32_t b[2]; b[0] = bp[0]; b[1] = bp[4];
                mma16(acc[0][j], a[0], b);
                mma16(acc[1][j], a[1], b);
            }
        }
    }
    __syncthreads();
    #pragma unroll
    for (int t2 = 0; t2 < 2; t2++) {
        int r = mw * 32 + t2 * 16 + g;
        #pragma unroll
        for (int j = 0; j < 4; j++) {
            int c = nw * 32 + j * 8 + q * 2;
            *(float2*)(Ys + r * LDP + c)       = make_float2(acc[t2][j][0], acc[t2][j][1]);
            *(float2*)(Ys + (r + 8) * LDP + c) = make_float2(acc[t2][j][2], acc[t2][j][3]);
        }
    }
    __syncthreads();
    for (int r = wid; r < 128; r += 16) {
        float4 y  = *(float4*)(Ys + r * LDP + lane * 4);
        float4 xv = *(const float4*)(X + (size_t)(row0 + r) * DM + lane * 4);
        float v0 = y.x + xv.x, v1 = y.y + xv.y, v2 = y.z + xv.z, v3 = y.w + xv.w;
        float s  = v0 + v1 + v2 + v3;
        float s2 = v0 * v0 + v1 * v1 + v2 * v2 + v3 * v3;
        #pragma unroll
        for (int off = 16; off; off >>= 1) {
            s  += __shfl_xor_sync(0xffffffffu, s,  off);
            s2 += __shfl_xor_sync(0xffffffffu, s2, off);
        }
        float mu = s * (1.f / DM);
        float var = s2 * (1.f / DM) - mu * mu;
        float rs = rsqrtf(var + 1e-5f);
        float4 gv = *(const float4*)(gamma + lane * 4);
        float4 bv = *(const float4*)(beta + lane * 4);
        float4 res = make_float4((v0 - mu) * rs * gv.x + bv.x,
                                 (v1 - mu) * rs * gv.y + bv.y,
                                 (v2 - mu) * rs * gv.z + bv.z,
                                 (v3 - mu) * rs * gv.w + bv.w);
        *(float4*)(out + (size_t)(row0 + r) * DM + lane * 4) = res;
    }
}

// ===========================================================================
extern "C" void kernel_launch(void* const* d_in, const int* in_sizes, int n_in,
                              void* d_out, int out_size) {
    const float* inputs = (const float*)d_in[0];
    const float* tm     = (const float*)d_in[2];
    const float* Wq     = (const float*)d_in[3];
    const float* Wk     = (const float*)d_in[4];
    const float* Wv     = (const float*)d_in[5];
    const float* Wo     = (const float*)d_in[6];
    const float* gamma  = (const float*)d_in[7];
    const float* beta   = (const float*)d_in[8];
    float* out = (float*)d_out;

    int smem_qkv  = 2 * 128 * LDH * (int)sizeof(uint32_t);    // 69632
    int smem_attn = 2 * 512 * 32 * (int)sizeof(uint32_t);     // 131072
    int smem_out  = 2 * 128 * LDH * (int)sizeof(uint32_t);    // 69632
    if (smem_out < 128 * LDP * (int)sizeof(float)) smem_out = 128 * LDP * (int)sizeof(float);
    cudaFuncSetAttribute(qkv_mma_kernel,     cudaFuncAttributeMaxDynamicSharedMemorySize, smem_qkv);
    cudaFuncSetAttribute(attn_kernel,        cudaFuncAttributeMaxDynamicSharedMemorySize, smem_attn);
    cudaFuncSetAttribute(outproj_mma_kernel, cudaFuncAttributeMaxDynamicSharedMemorySize, smem_out);

    convert_kernel<<<(XV + WV + WOV + 255) / 256, 256>>>(inputs, Wq, Wk, Wv, Wo);
    build_csr_kernel<<<(NT * NN * 32 + 255) / 256, 256>>>(tm);
    qkv_mma_kernel<<<dim3(NROWS / 128, 9), 256, smem_qkv>>>();
    attn_kernel<<<dim3(NH, NT * NB * NP), 512, smem_attn>>>();
    outproj_mma_kernel<<<NROWS / 128, 512, smem_out>>>(inputs, gamma, beta, out);
}

// round 17
// speedup vs baseline: 1.4590x; 1.4590x over previous
#include <cuda_runtime.h>
#include <cuda_fp16.h>
#include <math.h>
#include <stdint.h>

#define NB 4
#define NP 8
#define NN 512
#define DM 128
#define NH 4
#define DK 32
#define NT 3
#define NROWS (NB*NP*NN)     // 16384
#define MAXNNZ 128
#define LISTD 132
#define LDP 132              // smem row stride (floats) for fp32 epilogue scratch
#define LDH 68               // smem row stride (uint32 = half2) for fp16 tiles

// Scratch (device globals). fp16 intermediates to halve HBM traffic.
__device__ __half g_Xh[NROWS][DM];       // inputs pre-converted to fp16
__device__ __half g_Wh[9][DM][DM];       // Wq/Wk/Wv pre-converted to fp16
__device__ __half g_Woh[DM][NT*DM];      // Wo pre-converted to fp16
__device__ __half g_qkv[9][NROWS][DM];   // [t*3 + {Q,K,V}][row][d]
__device__ __half g_attn[NT][NROWS][DM]; // per-t attention output (fp16)
__device__ int    g_nnz[NT][NN];
__device__ int    g_colsT[NT][LISTD][NN];   // [t][i][n] -> coalesced over n
__device__ float  g_valsT[NT][LISTD][NN];

__constant__ int c_which[NT] = {0, 1, 3};

// ---------------------------------------------------------------------------
__device__ __forceinline__ uint32_t pack_h2(float a, float b) {
    __half2 h = __floats2half2_rn(a, b);
    return *(uint32_t*)&h;
}
__device__ __forceinline__ __half2 u2h2(uint32_t u) { return *(__half2*)&u; }
// m16n8k16 fp16 MMA, fp32 accum, D += A*B (row x col)
__device__ __forceinline__ void mma16(float d[4], const uint32_t a[4], const uint32_t b[2]) {
    asm volatile("mma.sync.aligned.m16n8k16.row.col.f32.f16.f16.f32 "
        "{%0,%1,%2,%3}, {%4,%5,%6,%7}, {%8,%9}, {%0,%1,%2,%3};"
        : "+f"(d[0]), "+f"(d[1]), "+f"(d[2]), "+f"(d[3])
        : "r"(a[0]), "r"(a[1]), "r"(a[2]), "r"(a[3]), "r"(b[0]), "r"(b[1]));
}

// ===========================================================================
// Kernel 0: pre-convert X, the 9 QKV weight slots, and Wo to fp16.
// ===========================================================================
#define XV  (NROWS*DM/8)     // 262144
#define WV  (9*DM*DM/8)      // 18432
#define WOV (DM*NT*DM/8)     // 6144
__global__ void convert_kernel(const float* __restrict__ X,
                               const float* __restrict__ Wq,
                               const float* __restrict__ Wk,
                               const float* __restrict__ Wv,
                               const float* __restrict__ Wo) {
    int idx = blockIdx.x * blockDim.x + threadIdx.x;
    if (idx < XV) {
        const float4* s = (const float4*)X + (size_t)idx * 2;
        float4 a = s[0], b = s[1];
        uint4 p = make_uint4(pack_h2(a.x, a.y), pack_h2(a.z, a.w),
                             pack_h2(b.x, b.y), pack_h2(b.z, b.w));
        *(uint4*)(&g_Xh[0][0] + (size_t)idx * 8) = p;
    } else if (idx < XV + WV) {
        int w = idx - XV;
        int slot = w / (DM * DM / 8);
        int off  = w % (DM * DM / 8);
        const float* Wb3[3] = {Wq, Wk, Wv};
        const float4* s = (const float4*)(Wb3[slot % 3] + (size_t)(slot / 3) * DM * DM) + (size_t)off * 2;
        float4 a = s[0], b = s[1];
        uint4 p = make_uint4(pack_h2(a.x, a.y), pack_h2(a.z, a.w),
                             pack_h2(b.x, b.y), pack_h2(b.z, b.w));
        *(uint4*)(&g_Wh[slot][0][0] + (size_t)off * 8) = p;
    } else if (idx < XV + WV + WOV) {
        int off = idx - XV - WV;
        const float4* s = (const float4*)Wo + (size_t)off * 2;
        float4 a = s[0], b = s[1];
        uint4 p = make_uint4(pack_h2(a.x, a.y), pack_h2(a.z, a.w),
                             pack_h2(b.x, b.y), pack_h2(b.z, b.w));
        *(uint4*)(&g_Woh[0][0] + (size_t)off * 8) = p;
    }
}

// ===========================================================================
// Kernel 1: build transposed CSR of the selected transition matrices.
// ===========================================================================
__global__ void build_csr_kernel(const float* __restrict__ tmall) {
    int wg   = (blockIdx.x * blockDim.x + threadIdx.x) >> 5;
    int lane = threadIdx.x & 31;
    if (wg >= NT * NN) return;
    int t = wg / NN, n = wg % NN;
    const float* row = tmall + ((size_t)c_which[t] * NN + n) * NN;
    int cnt = 0;
    for (int base = 0; base < NN; base += 32) {
        float v = row[base + lane];
        unsigned b = __ballot_sync(0xffffffffu, v != 0.0f);
        if (v != 0.0f) {
            int pos = cnt + __popc(b & ((1u << lane) - 1u));
            if (pos < MAXNNZ) { g_colsT[t][pos][n] = base + lane; g_valsT[t][pos][n] = v; }
        }
        cnt += __popc(b);
    }
    if (lane == 0) g_nnz[t][n] = cnt < MAXNNZ ? cnt : MAXNNZ;
}

// ===========================================================================
// Kernel 2: QKV projections via fp16 mma.sync m16n8k16 (R15 shape).
// grid = (256 tiles, 9 slots); 256 threads / 8 warps (2m x 4n of 32x32);
// 3 CTAs/SM (51KB smem). fp16 out.
// ===========================================================================
__global__ void __launch_bounds__(256, 3)
qkv_mma_kernel() {
    extern __shared__ uint32_t sm[];
    uint32_t* Xh = sm;                // [64][LDH]
    uint32_t* Wh = sm + 64 * LDH;     // [128][LDH]
    int tid = threadIdx.x, lane = tid & 31, wid = tid >> 5;
    int mw = wid & 1, nw = wid >> 1;
    int g = lane >> 2, q = lane & 3;
    int slot = blockIdx.y;
    int row0 = blockIdx.x * 64;

    const __half* Xg = &g_Xh[row0][0];
    for (int i = tid; i < 64 * 16; i += 256) {
        int r = i >> 4, c = i & 15;
        uint4 v = *(const uint4*)(Xg + (size_t)r * DM + c * 8);
        *(uint4*)(Xh + r * LDH + c * 4) = v;
    }
    const __half* Wg = &g_Wh[slot][0][0];
    for (int i = tid; i < 128 * 16; i += 256) {
        int r = i >> 4, c = i & 15;
        uint4 v = *(const uint4*)(Wg + (size_t)r * DM + c * 8);
        *(uint4*)(Wh + r * LDH + c * 4) = v;
    }
    __syncthreads();

    const uint32_t* abase = Xh + (mw * 32 + g) * LDH + q;
    const uint32_t* bbase = Wh + (nw * 32 + g) * LDH + q;

    float acc[2][4][4];
    #pragma unroll
    for (int t2 = 0; t2 < 2; t2++)
        #pragma unroll
        for (int j = 0; j < 4; j++)
            #pragma unroll
            for (int e = 0; e < 4; e++) acc[t2][j][e] = 0.f;

    #pragma unroll
    for (int ks = 0; ks < 8; ks++) {
        int k0 = ks * 8;
        uint32_t a[2][4];
        #pragma unroll
        for (int t2 = 0; t2 < 2; t2++) {
            const uint32_t* ap = abase + t2 * 16 * LDH + k0;
            a[t2][0] = ap[0];            a[t2][1] = ap[8 * LDH];
            a[t2][2] = ap[4];            a[t2][3] = ap[8 * LDH + 4];
        }
        #pragma unroll
        for (int j = 0; j < 4; j++) {
            const uint32_t* bp = bbase + j * 8 * LDH + k0;
            uint32_t b[2]; b[0] = bp[0]; b[1] = bp[4];
            mma16(acc[0][j], a[0], b);
            mma16(acc[1][j], a[1], b);
        }
    }
    __half* outh = &g_qkv[slot][row0][0];
    #pragma unroll
    for (int t2 = 0; t2 < 2; t2++) {
        int r = mw * 32 + t2 * 16 + g;
        #pragma unroll
        for (int j = 0; j < 4; j++) {
            int c = nw * 32 + j * 8 + q * 2;
            *(uint32_t*)(outh + (size_t)r * DM + c)       = pack_h2(acc[t2][j][0], acc[t2][j][1]);
            *(uint32_t*)(outh + (size_t)(r + 8) * DM + c) = pack_h2(acc[t2][j][2], acc[t2][j][3]);
        }
    }
}

// ===========================================================================
// Kernel 3: sparse-masked attention (R15 structure, unchanged).
//  - K in fp16 SMEM, duplicated-row layout (4 LDS.128/entry, 4-phase);
//    dot via 16 HFMA2 in 4 parallel chains, combined in fp32.
//  - V in fp32 SMEM, rotated layout (8 LDS.128/entry, 4-phase), fp32 FFMA.
// ===========================================================================
__global__ void __launch_bounds__(512, 1)
attn_kernel() {
    extern __shared__ uint32_t smw[];
    uint32_t* Ks = smw;                 // [512][32] uint32: 16 data + 16 dup
    float*    Vs = (float*)(smw + 512 * 32);  // [512][32] fp32
    int tid = threadIdx.x;
    int h = blockIdx.x;
    int t = blockIdx.y >> 5, bp = blockIdx.y & 31;

    const __half* Kg = &g_qkv[t * 3 + 1][(size_t)bp * NN][0];
    const __half* Vg = &g_qkv[t * 3 + 2][(size_t)bp * NN][0];
    for (int i = tid; i < 512 * 4; i += 512) {
        int m = i >> 2, c = i & 3;
        uint4 kk = *(const uint4*)(Kg + (size_t)m * DM + h * DK + c * 8);
        *(uint4*)(Ks + m * 32 + c * 4)      = kk;
        *(uint4*)(Ks + m * 32 + 16 + c * 4) = kk;
        uint4 vv = *(const uint4*)(Vg + (size_t)m * DM + h * DK + c * 8);
        float2 f0 = __half22float2(u2h2(vv.x));
        float2 f1 = __half22float2(u2h2(vv.y));
        float2 f2 = __half22float2(u2h2(vv.z));
        float2 f3 = __half22float2(u2h2(vv.w));
        *(float4*)(Vs + m * 32 + c * 8)     = make_float4(f0.x, f0.y, f1.x, f1.y);
        *(float4*)(Vs + m * 32 + c * 8 + 4) = make_float4(f2.x, f2.y, f3.x, f3.y);
    }
    __syncthreads();

    int n = tid;
    int gn = bp * NN + n;
    int rot4 = tid & 3;
    int copyoff = ((tid >> 2) & 1) * 16;
    int rot8 = tid & 7;
    const float scale = 0.17677669529663687f;
    const __half2 sh2 = __float2half2_rn(scale);

    __half2 qh[16];
    const __half* Qg = &g_qkv[t * 3 + 0][gn][h * DK];
    #pragma unroll
    for (int c = 0; c < 4; c++) {
        int cc = (c + rot4) & 3;
        uint4 qv = *(const uint4*)(Qg + cc * 8);
        qh[c * 4 + 0] = __hmul2(u2h2(qv.x), sh2);
        qh[c * 4 + 1] = __hmul2(u2h2(qv.y), sh2);
        qh[c * 4 + 2] = __hmul2(u2h2(qv.z), sh2);
        qh[c * 4 + 3] = __hmul2(u2h2(qv.w), sh2);
    }
    int cnt = g_nnz[t][n];
    float Z = 0.f;
    float4 av[8];
    #pragma unroll
    for (int j = 0; j < 8; j++) av[j] = make_float4(0.f, 0.f, 0.f, 0.f);

    for (int i = 0; i < cnt; i++) {
        int m = g_colsT[t][i][n];
        float tv = g_valsT[t][i][n];
        const uint32_t* kb = Ks + m * 32 + copyoff;
        __half2 hacc[4];
        #pragma unroll
        for (int c = 0; c < 4; c++) {
            uint4 kk = *(const uint4*)(kb + ((c + rot4) & 3) * 4);
            __half2 a = __hmul2(qh[c * 4 + 0], u2h2(kk.x));
            a = __hfma2(qh[c * 4 + 1], u2h2(kk.y), a);
            a = __hfma2(qh[c * 4 + 2], u2h2(kk.z), a);
            a = __hfma2(qh[c * 4 + 3], u2h2(kk.w), a);
            hacc[c] = a;
        }
        float2 f0 = __half22float2(hacc[0]);
        float2 f1 = __half22float2(hacc[1]);
        float2 f2 = __half22float2(hacc[2]);
        float2 f3 = __half22float2(hacc[3]);
        float s = ((f0.x + f0.y) + (f1.x + f1.y)) + ((f2.x + f2.y) + (f3.x + f3.y));
        float e = __expf(s);
        Z += e;
        float we = tv * e;
        const float* vb = Vs + m * 32;
        #pragma unroll
        for (int j = 0; j < 8; j++) {
            int jj = (j + rot8) & 7;
            float4 v4 = *(const float4*)(vb + jj * 4);
            av[j].x += we * v4.x;
            av[j].y += we * v4.y;
            av[j].z += we * v4.z;
            av[j].w += we * v4.w;
        }
    }
    float inv = 1.f / Z;
    __half* outh = &g_attn[t][gn][h * DK];
    #pragma unroll
    for (int j = 0; j < 8; j += 2) {
        int j0 = (j + rot8) & 7, j1 = (j + 1 + rot8) & 7;
        *(uint2*)(outh + j0 * 4) = make_uint2(pack_h2(av[j].x * inv, av[j].y * inv),
                                              pack_h2(av[j].z * inv, av[j].w * inv));
        *(uint2*)(outh + j1 * 4) = make_uint2(pack_h2(av[j+1].x * inv, av[j+1].y * inv),
                                              pack_h2(av[j+1].z * inv, av[j+1].w * inv));
    }
}

// ===========================================================================
// Kernel 4: output projection via fp16 mma.sync m16n8k16 (K=384 = 3
// accumulated chunks), 512 threads / 16 warps; A and W both staged as raw
// uint4 copies from fp16 globals. Fused residual + warp-per-row LN.
// ===========================================================================
__global__ void __launch_bounds__(512, 1)
outproj_mma_kernel(const float* __restrict__ X,
                   const float* __restrict__ gamma,
                   const float* __restrict__ beta,
                   float* __restrict__ out) {
    extern __shared__ uint32_t sm[];
    uint32_t* As = sm;                 // [128][LDH]
    uint32_t* Ws = sm + 128 * LDH;     // [128][LDH]
    float* Ys = (float*)sm;            // reuse (LDP stride) after GEMM
    int tid = threadIdx.x, lane = tid & 31, wid = tid >> 5;
    int mw = wid & 3, nw = wid >> 2;
    int g = lane >> 2, q = lane & 3;
    int row0 = blockIdx.x * 128;

    const uint32_t* abase = As + (mw * 32 + g) * LDH + q;
    const uint32_t* bbase = Ws + (nw * 32 + g) * LDH + q;

    float acc[2][4][4];
    #pragma unroll
    for (int t2 = 0; t2 < 2; t2++)
        #pragma unroll
        for (int j = 0; j < 4; j++)
            #pragma unroll
            for (int e = 0; e < 4; e++) acc[t2][j][e] = 0.f;

    for (int t = 0; t < NT; t++) {
        __syncthreads();
        for (int i = tid; i < 128 * 16; i += 512) {
            int r = i >> 4, c = i & 15;
            uint4 a = *(const uint4*)(&g_attn[t][row0 + r][c * 8]);
            *(uint4*)(As + r * LDH + c * 4) = a;
        }
        for (int i = tid; i < 128 * 16; i += 512) {
            int r = i >> 4, c = i & 15;
            uint4 w = *(const uint4*)(&g_Woh[r][t * DM + c * 8]);
            *(uint4*)(Ws + r * LDH + c * 4) = w;
        }
        __syncthreads();
        #pragma unroll
        for (int ks = 0; ks < 8; ks++) {
            int k0 = ks * 8;
            uint32_t a[2][4];
            #pragma unroll
            for (int t2 = 0; t2 < 2; t2++) {
                const uint32_t* ap = abase + t2 * 16 * LDH + k0;
                a[t2][0] = ap[0];            a[t2][1] = ap[8 * LDH];
                a[t2][2] = ap[4];            a[t2][3] = ap[8 * LDH + 4];
            }
            #pragma unroll
            for (int j = 0; j < 4; j++) {
                const uint32_t* bp = bbase + j * 8 * LDH + k0;
                uint32_t b[2]; b[0] = bp[0]; b[1] = bp[4];
                mma16(acc[0][j], a[0], b);
                mma16(acc[1][j], a[1], b);
            }
        }
    }
    __syncthreads();
    #pragma unroll
    for (int t2 = 0; t2 < 2; t2++) {
        int r = mw * 32 + t2 * 16 + g;
        #pragma unroll
        for (int j = 0; j < 4; j++) {
            int c = nw * 32 + j * 8 + q * 2;
            *(float2*)(Ys + r * LDP + c)       = make_float2(acc[t2][j][0], acc[t2][j][1]);
            *(float2*)(Ys + (r + 8) * LDP + c) = make_float2(acc[t2][j][2], acc[t2][j][3]);
        }
    }
    __syncthreads();
    for (int r = wid; r < 128; r += 16) {
        float4 y  = *(float4*)(Ys + r * LDP + lane * 4);
        float4 xv = *(const float4*)(X + (size_t)(row0 + r) * DM + lane * 4);
        float v0 = y.x + xv.x, v1 = y.y + xv.y, v2 = y.z + xv.z, v3 = y.w + xv.w;
        float s  = v0 + v1 + v2 + v3;
        float s2 = v0 * v0 + v1 * v1 + v2 * v2 + v3 * v3;
        #pragma unroll
        for (int off = 16; off; off >>= 1) {
            s  += __shfl_xor_sync(0xffffffffu, s,  off);
            s2 += __shfl_xor_sync(0xffffffffu, s2, off);
        }
        float mu = s * (1.f / DM);
        float var = s2 * (1.f / DM) - mu * mu;
        float rs = rsqrtf(var + 1e-5f);
        float4 gv = *(const float4*)(gamma + lane * 4);
        float4 bv = *(const float4*)(beta + lane * 4);
        float4 res = make_float4((v0 - mu) * rs * gv.x + bv.x,
                                 (v1 - mu) * rs * gv.y + bv.y,
                                 (v2 - mu) * rs * gv.z + bv.z,
                                 (v3 - mu) * rs * gv.w + bv.w);
        *(float4*)(out + (size_t)(row0 + r) * DM + lane * 4) = res;
    }
}

// ===========================================================================
extern "C" void kernel_launch(void* const* d_in, const int* in_sizes, int n_in,
                              void* d_out, int out_size) {
    const float* inputs = (const float*)d_in[0];
    const float* tm     = (const float*)d_in[2];
    const float* Wq     = (const float*)d_in[3];
    const float* Wk     = (const float*)d_in[4];
    const float* Wv     = (const float*)d_in[5];
    const float* Wo     = (const float*)d_in[6];
    const float* gamma  = (const float*)d_in[7];
    const float* beta   = (const float*)d_in[8];
    float* out = (float*)d_out;

    int smem_qkv  = (64 + 128) * LDH * (int)sizeof(uint32_t); // 52224
    int smem_attn = 2 * 512 * 32 * (int)sizeof(uint32_t);     // 131072
    int smem_out  = 2 * 128 * LDH * (int)sizeof(uint32_t);    // 69632
    if (smem_out < 128 * LDP * (int)sizeof(float)) smem_out = 128 * LDP * (int)sizeof(float);
    cudaFuncSetAttribute(qkv_mma_kernel,     cudaFuncAttributeMaxDynamicSharedMemorySize, smem_qkv);
    cudaFuncSetAttribute(attn_kernel,        cudaFuncAttributeMaxDynamicSharedMemorySize, smem_attn);
    cudaFuncSetAttribute(outproj_mma_kernel, cudaFuncAttributeMaxDynamicSharedMemorySize, smem_out);

    convert_kernel<<<(XV + WV + WOV + 255) / 256, 256>>>(inputs, Wq, Wk, Wv, Wo);
    build_csr_kernel<<<(NT * NN * 32 + 255) / 256, 256>>>(tm);
    qkv_mma_kernel<<<dim3(NROWS / 64, 9), 256, smem_qkv>>>();
    attn_kernel<<<dim3(NH, NT * NB * NP), 512, smem_attn>>>();
    outproj_mma_kernel<<<NROWS / 128, 512, smem_out>>>(inputs, gamma, beta, out);
}